// round 2
// baseline (speedup 1.0000x reference)
#include <cuda_runtime.h>
#include <cuda_bf16.h>
#include <cstddef>

// Problem constants
#define NN_NODES 10000
#define IN_C     256
#define C1       128      // 2*OUT_C
#define OUT_C    64
#define NE       640000

// ---------------- scratch (static device globals; no allocation) ------------
__device__ float g_h   [NN_NODES * IN_C];   // relu(x@Wt+bt)
__device__ float g_tx1 [NN_NODES * IN_C];   // L_hat @ h
__device__ float g_h2  [NN_NODES * C1];     // relu(cheb1)
__device__ float g_tx2 [NN_NODES * C1];     // L_hat @ h2
__device__ int   g_outdeg[NN_NODES];
__device__ int   g_indeg [NN_NODES];
__device__ float g_dinv  [NN_NODES];
__device__ int   g_rowstart[NN_NODES + 1];
__device__ int   g_cursor  [NN_NODES];
__device__ int   g_srcs [NE];               // src sorted by dst
__device__ float g_ws   [NE];               // edge weight sorted by dst

// ---------------- small kernels --------------------------------------------
__global__ void k_zero_deg(int n) {
    int i = blockIdx.x * blockDim.x + threadIdx.x;
    if (i < n) { g_outdeg[i] = 0; g_indeg[i] = 0; }
}

__global__ void k_count(const int* __restrict__ ei) {
    int e = blockIdx.x * blockDim.x + threadIdx.x;
    if (e < NE) {
        atomicAdd(&g_outdeg[ei[e]], 1);
        atomicAdd(&g_indeg[ei[NE + e]], 1);
    }
}

__global__ void k_dinv(int n) {
    int i = blockIdx.x * blockDim.x + threadIdx.x;
    if (i < n) {
        int d = g_outdeg[i];
        g_dinv[i] = (d > 0) ? rsqrtf((float)d) : 0.0f;
    }
}

// single-block exclusive scan of indeg -> rowstart, cursor
__global__ void k_scan(int n) {
    __shared__ int sh[1024];
    __shared__ int carry_s;
    int tid = threadIdx.x;
    if (tid == 0) carry_s = 0;
    __syncthreads();
    for (int base = 0; base < n; base += 1024) {
        int i = base + tid;
        int v = (i < n) ? g_indeg[i] : 0;
        sh[tid] = v;
        __syncthreads();
        for (int off = 1; off < 1024; off <<= 1) {
            int t = (tid >= off) ? sh[tid - off] : 0;
            __syncthreads();
            sh[tid] += t;
            __syncthreads();
        }
        int carry = carry_s;
        int excl  = carry + sh[tid] - v;
        if (i < n) { g_rowstart[i] = excl; g_cursor[i] = excl; }
        __syncthreads();
        if (tid == 0) carry_s = carry + sh[1023];
        __syncthreads();
    }
    if (tid == 0) g_rowstart[n] = carry_s;
}

__global__ void k_bucket(const int* __restrict__ ei) {
    int e = blockIdx.x * blockDim.x + threadIdx.x;
    if (e < NE) {
        int s = ei[e];
        int d = ei[NE + e];
        int pos = atomicAdd(&g_cursor[d], 1);
        g_srcs[pos] = s;
        g_ws[pos]   = -g_dinv[s] * g_dinv[d];
    }
}

// ---------------- SpMM: one block per dst row, one thread per channel ------
template <int CH>
__global__ void __launch_bounds__(CH) k_spmm(const float* __restrict__ h,
                                             float* __restrict__ tx) {
    int d = blockIdx.x;
    int c = threadIdx.x;
    int beg = g_rowstart[d];
    int end = g_rowstart[d + 1];
    float acc = 0.0f;
    int j = beg;
    for (; j + 4 <= end; j += 4) {
        int   s0 = g_srcs[j],   s1 = g_srcs[j+1], s2 = g_srcs[j+2], s3 = g_srcs[j+3];
        float w0 = g_ws[j],     w1 = g_ws[j+1],   w2 = g_ws[j+2],   w3 = g_ws[j+3];
        float h0 = h[(size_t)s0 * CH + c];
        float h1 = h[(size_t)s1 * CH + c];
        float h2 = h[(size_t)s2 * CH + c];
        float h3 = h[(size_t)s3 * CH + c];
        acc += w0 * h0; acc += w1 * h1; acc += w2 * h2; acc += w3 * h3;
    }
    for (; j < end; ++j)
        acc += g_ws[j] * h[(size_t)g_srcs[j] * CH + c];
    tx[(size_t)d * CH + c] = acc;
}

// ---------------- tiled SGEMM: C = act(A1@B1 [+ A2@B2] + bias) -------------
// A row-major MxK (lda=K), B row-major KxN (ldb=N), C row-major MxN.
template <int BM, int BN, int BK, int TM, int TN, bool RELU>
__global__ void __launch_bounds__((BM / TM) * (BN / TN))
k_gemm(const float* __restrict__ A1, const float* __restrict__ B1,
       const float* __restrict__ A2, const float* __restrict__ B2,
       const float* __restrict__ bias, float* __restrict__ C,
       int M, int N, int K) {
    constexpr int NT = (BM / TM) * (BN / TN);
    __shared__ float As[BK][BM];
    __shared__ float Bs[BK][BN];

    const int tid = threadIdx.x;
    const int m0  = blockIdx.y * BM;
    const int n0  = blockIdx.x * BN;
    const int tr  = tid / (BN / TN);
    const int tc  = tid % (BN / TN);
    const int rowBase = tr * TM;
    const int colBase = tc * TN;

    float acc[TM][TN];
#pragma unroll
    for (int i = 0; i < TM; i++)
#pragma unroll
        for (int j = 0; j < TN; j++) acc[i][j] = 0.0f;

    const int nphase = (A2 != nullptr) ? 2 : 1;
    for (int phase = 0; phase < nphase; ++phase) {
        const float* __restrict__ A = phase ? A2 : A1;
        const float* __restrict__ B = phase ? B2 : B1;
        for (int k0 = 0; k0 < K; k0 += BK) {
            // load A tile (BM x BK), float4 along K, store transposed
            constexpr int AIT = (BM * BK / 4) / NT;
#pragma unroll
            for (int it = 0; it < AIT; ++it) {
                int idx = tid + it * NT;
                int ar  = idx / (BK / 4);
                int akg = idx % (BK / 4);
                int grow = m0 + ar;
                float4 f = make_float4(0.f, 0.f, 0.f, 0.f);
                if (grow < M)
                    f = *reinterpret_cast<const float4*>(A + (size_t)grow * K + k0 + akg * 4);
                As[akg * 4 + 0][ar] = f.x;
                As[akg * 4 + 1][ar] = f.y;
                As[akg * 4 + 2][ar] = f.z;
                As[akg * 4 + 3][ar] = f.w;
            }
            // load B tile (BK x BN), scalar coalesced
            constexpr int BIT = (BK * BN) / NT;
#pragma unroll
            for (int it = 0; it < BIT; ++it) {
                int idx = tid + it * NT;
                int br = idx / BN;
                int bc = idx % BN;
                Bs[br][bc] = B[(size_t)(k0 + br) * N + n0 + bc];
            }
            __syncthreads();
#pragma unroll
            for (int k = 0; k < BK; k++) {
                float ra[TM], rb[TN];
#pragma unroll
                for (int i = 0; i < TM; i++) ra[i] = As[k][rowBase + i];
#pragma unroll
                for (int j = 0; j < TN; j++) rb[j] = Bs[k][colBase + j];
#pragma unroll
                for (int i = 0; i < TM; i++)
#pragma unroll
                    for (int j = 0; j < TN; j++)
                        acc[i][j] += ra[i] * rb[j];
            }
            __syncthreads();
        }
    }

    float bv[TN];
#pragma unroll
    for (int j = 0; j < TN; j++) bv[j] = bias[n0 + colBase + j];

#pragma unroll
    for (int i = 0; i < TM; i++) {
        int grow = m0 + rowBase + i;
        if (grow < M) {
            float4 o;
            float v0 = acc[i][0] + bv[0];
            float v1 = acc[i][1] + bv[1];
            float v2 = acc[i][2] + bv[2];
            float v3 = acc[i][3] + bv[3];
            if (RELU) {
                v0 = fmaxf(v0, 0.f); v1 = fmaxf(v1, 0.f);
                v2 = fmaxf(v2, 0.f); v3 = fmaxf(v3, 0.f);
            }
            o.x = v0; o.y = v1; o.z = v2; o.w = v3;
            *reinterpret_cast<float4*>(C + (size_t)grow * N + n0 + colBase) = o;
        }
    }
}

// ---------------- launcher --------------------------------------------------
extern "C" void kernel_launch(void* const* d_in, const int* in_sizes, int n_in,
                              void* d_out, int out_size) {
    const float* x    = (const float*)d_in[0];
    const int*   ei   = (const int*)d_in[1];
    const float* Wt   = (const float*)d_in[2];
    const float* bt   = (const float*)d_in[3];
    const float* W0_1 = (const float*)d_in[4];
    const float* W1_1 = (const float*)d_in[5];
    const float* b1   = (const float*)d_in[6];
    const float* W0mu = (const float*)d_in[7];
    const float* W1mu = (const float*)d_in[8];
    const float* bmu  = (const float*)d_in[9];
    const float* W0ls = (const float*)d_in[10];
    const float* W1ls = (const float*)d_in[11];
    const float* bls  = (const float*)d_in[12];
    float* out = (float*)d_out;

    float* h   = nullptr; float* tx1 = nullptr; float* h2 = nullptr; float* tx2 = nullptr;
    // resolve device symbol addresses (host-side, no allocation)
    cudaGetSymbolAddress((void**)&h,   g_h);
    cudaGetSymbolAddress((void**)&tx1, g_tx1);
    cudaGetSymbolAddress((void**)&h2,  g_h2);
    cudaGetSymbolAddress((void**)&tx2, g_tx2);

    const int TPB = 256;

    // graph preprocessing
    k_zero_deg<<<(NN_NODES + TPB - 1) / TPB, TPB>>>(NN_NODES);
    k_count<<<(NE + TPB - 1) / TPB, TPB>>>(ei);
    k_dinv<<<(NN_NODES + TPB - 1) / TPB, TPB>>>(NN_NODES);
    k_scan<<<1, 1024>>>(NN_NODES);
    k_bucket<<<(NE + TPB - 1) / TPB, TPB>>>(ei);

    // h = relu(x @ Wt + bt)   [10000, 256]
    {
        dim3 grid(IN_C / 64, (NN_NODES + 127) / 128);
        k_gemm<128, 64, 8, 8, 4, true><<<grid, 256>>>(
            x, Wt, nullptr, nullptr, bt, h, NN_NODES, IN_C, NN_NODES);
    }
    // tx1 = L_hat @ h
    k_spmm<IN_C><<<NN_NODES, IN_C>>>(h, tx1);
    // h2 = relu(h @ W0_1 + tx1 @ W1_1 + b1)   [10000, 128]
    {
        dim3 grid(C1 / 64, (NN_NODES + 127) / 128);
        k_gemm<128, 64, 8, 8, 4, true><<<grid, 256>>>(
            h, W0_1, tx1, W1_1, b1, h2, NN_NODES, C1, IN_C);
    }
    // tx2 = L_hat @ h2 (shared by mu and logstd)
    k_spmm<C1><<<NN_NODES, C1>>>(h2, tx2);
    // mu / logstd   [10000, 64] each
    {
        dim3 grid(OUT_C / 64, (NN_NODES + 127) / 128);
        k_gemm<128, 64, 8, 8, 4, false><<<grid, 256>>>(
            h2, W0mu, tx2, W1mu, bmu, out, NN_NODES, OUT_C, C1);
        k_gemm<128, 64, 8, 8, 4, false><<<grid, 256>>>(
            h2, W0ls, tx2, W1ls, bls, out + NN_NODES * OUT_C, NN_NODES, OUT_C, C1);
    }
}

// round 4
// speedup vs baseline: 1.0822x; 1.0822x over previous
#include <cuda_runtime.h>
#include <cuda_bf16.h>
#include <cstdint>
#include <cstddef>

// ---------------- problem constants ----------------
#define NN_NODES 10000
#define IN_C     256
#define C1       128
#define OUT_C    64
#define NE       640000
#define KPAD     10048          // padded K for B (zero-filled)
#define BKC      32             // K per mainloop chunk
#define CH1      313            // ceil(10000/32)

// ---------------- PTX helpers ----------------
__device__ __forceinline__ uint32_t smem_u32(const void* p) {
    uint32_t a;
    asm("{ .reg .u64 t; cvta.to.shared.u64 t, %1; cvt.u32.u64 %0, t; }" : "=r"(a) : "l"(p));
    return a;
}
__device__ __forceinline__ void ldm_x4(uint32_t& r0, uint32_t& r1, uint32_t& r2, uint32_t& r3,
                                       uint32_t addr) {
    asm volatile("ldmatrix.sync.aligned.m8n8.x4.shared.b16 {%0,%1,%2,%3}, [%4];"
                 : "=r"(r0), "=r"(r1), "=r"(r2), "=r"(r3) : "r"(addr));
}
__device__ __forceinline__ void mma16816(float* d, const uint32_t* a, const uint32_t* b) {
    asm volatile("mma.sync.aligned.m16n8k16.row.col.f32.bf16.bf16.f32 "
                 "{%0,%1,%2,%3}, {%4,%5,%6,%7}, {%8,%9}, {%0,%1,%2,%3};"
                 : "+f"(d[0]), "+f"(d[1]), "+f"(d[2]), "+f"(d[3])
                 : "r"(a[0]), "r"(a[1]), "r"(a[2]), "r"(a[3]), "r"(b[0]), "r"(b[1]));
}
#define CP16(dst, src) \
    asm volatile("cp.async.cg.shared.global [%0], [%1], 16;" :: "r"(dst), "l"(src))
#define CP_COMMIT() asm volatile("cp.async.commit_group;")
#define CP_WAIT0()  asm volatile("cp.async.wait_group 0;")

// ---------------- scratch globals ----------------
__device__ float g_h   [NN_NODES * IN_C];
__device__ float g_tx1 [NN_NODES * IN_C];
__device__ float g_h2  [NN_NODES * C1];
__device__ float g_tx2 [NN_NODES * C1];
__device__ int   g_outdeg[NN_NODES];
__device__ int   g_indeg [NN_NODES];
__device__ float g_dinv  [NN_NODES];
__device__ int   g_rowstart[NN_NODES + 1];
__device__ int   g_cursor  [NN_NODES];
__device__ int   g_srcs [NE];
__device__ float g_ws   [NE];
__device__ __nv_bfloat16 g_BT_hi[256 * KPAD];   // Wt^T split-hi, [n][k]
__device__ __nv_bfloat16 g_BT_lo[256 * KPAD];   // Wt^T split-lo

// ---------------- preprocessing kernels ----------------
__global__ void k_zero_deg(int n) {
    int i = blockIdx.x * blockDim.x + threadIdx.x;
    if (i < n) { g_outdeg[i] = 0; g_indeg[i] = 0; }
}
__global__ void k_count(const int* __restrict__ ei) {
    int e = blockIdx.x * blockDim.x + threadIdx.x;
    if (e < NE) {
        atomicAdd(&g_outdeg[ei[e]], 1);
        atomicAdd(&g_indeg[ei[NE + e]], 1);
    }
}
__global__ void k_dinv(int n) {
    int i = blockIdx.x * blockDim.x + threadIdx.x;
    if (i < n) {
        int d = g_outdeg[i];
        g_dinv[i] = (d > 0) ? rsqrtf((float)d) : 0.0f;
    }
}
// one-pass scan: each thread owns 10 rows
__global__ void k_scan(int n) {
    __shared__ int sh[1024];
    int t = threadIdx.x;
    const int per = 10;
    int base = t * per;
    int loc[10];
    int s = 0;
#pragma unroll
    for (int i = 0; i < per; i++) {
        int idx = base + i;
        int v = (idx < n) ? g_indeg[idx] : 0;
        loc[i] = s; s += v;
    }
    sh[t] = s;
    __syncthreads();
    for (int off = 1; off < 1024; off <<= 1) {
        int v = (t >= off) ? sh[t - off] : 0;
        __syncthreads();
        sh[t] += v;
        __syncthreads();
    }
    int bb = (t > 0) ? sh[t - 1] : 0;
#pragma unroll
    for (int i = 0; i < per; i++) {
        int idx = base + i;
        if (idx < n) { int v = bb + loc[i]; g_rowstart[idx] = v; g_cursor[idx] = v; }
    }
    if (t == 1023) g_rowstart[n] = sh[1023];
}
__global__ void k_bucket(const int* __restrict__ ei) {
    int e = blockIdx.x * blockDim.x + threadIdx.x;
    if (e < NE) {
        int s = ei[e];
        int d = ei[NE + e];
        int pos = atomicAdd(&g_cursor[d], 1);
        g_srcs[pos] = s;
        g_ws[pos]   = -g_dinv[s] * g_dinv[d];
    }
}

// Wt [10000,256] fp32 -> transposed bf16 hi/lo [256][KPAD]
__global__ void k_convW(const float* __restrict__ Wt) {
    __shared__ float tile[32][33];
    int bx = blockIdx.x, by = blockIdx.y;
    int tx = threadIdx.x, ty = threadIdx.y;
    int gk = bx * 32 + ty;
    int gn = by * 32 + tx;
    tile[ty][tx] = (gk < NN_NODES) ? Wt[(size_t)gk * 256 + gn] : 0.0f;
    __syncthreads();
    int n = by * 32 + ty;
    int k = bx * 32 + tx;
    float v = tile[tx][ty];
    __nv_bfloat16 hi = __float2bfloat16(v);
    __nv_bfloat16 lo = __float2bfloat16(v - __bfloat162float(hi));
    g_BT_hi[(size_t)n * KPAD + k] = hi;
    g_BT_lo[(size_t)n * KPAD + k] = lo;
}

// ---------------- GEMM1 via mma.sync bf16 (3-term split) --------------------
// H = relu(X @ Wt + bt). CTA tile 128x128, BK=32, 2-stage smem pipeline.
// smem per stage (pitch 80B/row): Ahi@0, Alo@10240, Bhi@20480, Blo@30720.
#define G1_STG   40960
#define G1_SMEM  (2 * G1_STG)
#define PITCH    80

__global__ void __launch_bounds__(256, 1)
k_gemm1_mma(const float* __restrict__ X, const float* __restrict__ bt,
            float* __restrict__ H) {
    extern __shared__ char smem[];
    const uint32_t sb = smem_u32(smem);
    const int tid  = threadIdx.x;
    const int wid  = tid >> 5, lane = tid & 31;
    const int m0   = blockIdx.y * 128;
    const int n0g  = blockIdx.x * 128;
    const int warp_m = (wid >> 1) * 32;
    const int warp_n = (wid & 1) * 64;

    // per-thread load coords
    const int lr = tid >> 1;          // row 0..127
    const int lh = tid & 1;           // half selector

    // ldmatrix lane offsets
    const int La     = lane & 7;
    const int a_moff = ((lane >> 3) & 1) * 8 + La;
    const int a_koff = (lane >> 4) * 8;
    const int b_noff = (lane >> 4) * 8 + La;
    const int b_koff = ((lane >> 3) & 1) * 8;

    float acc[2][8][4];
#pragma unroll
    for (int i = 0; i < 2; i++)
#pragma unroll
        for (int j = 0; j < 8; j++)
#pragma unroll
            for (int q = 0; q < 4; q++) acc[i][j][q] = 0.0f;

    const char* bhsrc = (const char*)g_BT_hi;
    const char* blsrc = (const char*)g_BT_lo;
    const size_t brow = (size_t)KPAD * 2;

    float4 v[4];

    // ---- helpers as macros over locals ----
#define LDG_A(c) do {                                                           \
        int k0 = (c) * BKC;                                                     \
        int grow = m0 + lr;                                                     \
        _Pragma("unroll")                                                       \
        for (int i = 0; i < 4; i++) {                                           \
            int gk = k0 + lh * 16 + i * 4;                                      \
            v[i] = (grow < NN_NODES && gk < NN_NODES)                           \
                 ? *reinterpret_cast<const float4*>(X + (size_t)grow * NN_NODES + gk) \
                 : make_float4(0.f, 0.f, 0.f, 0.f);                             \
        }                                                                       \
    } while (0)

#define CPA_B(c, st) do {                                                       \
        int k0 = (c) * BKC;                                                     \
        uint32_t dsth = sb + (st) * G1_STG + 20480 + lr * PITCH + lh * 32;      \
        uint32_t dstl = dsth + 10240;                                           \
        const char* sh_ = bhsrc + (size_t)(n0g + lr) * brow + k0 * 2 + lh * 32; \
        const char* sl_ = blsrc + (size_t)(n0g + lr) * brow + k0 * 2 + lh * 32; \
        CP16(dsth, sh_); CP16(dsth + 16, sh_ + 16);                             \
        CP16(dstl, sl_); CP16(dstl + 16, sl_ + 16);                             \
        CP_COMMIT();                                                            \
    } while (0)

#define STS_A(st) do {                                                          \
        uint32_t dh = sb + (st) * G1_STG + lr * PITCH + lh * 32;                \
        _Pragma("unroll")                                                       \
        for (int i = 0; i < 4; i++) {                                           \
            __nv_bfloat16 h0 = __float2bfloat16(v[i].x);                        \
            __nv_bfloat16 h1 = __float2bfloat16(v[i].y);                        \
            __nv_bfloat16 h2 = __float2bfloat16(v[i].z);                        \
            __nv_bfloat16 h3 = __float2bfloat16(v[i].w);                        \
            __nv_bfloat16 l0 = __float2bfloat16(v[i].x - __bfloat162float(h0)); \
            __nv_bfloat16 l1 = __float2bfloat16(v[i].y - __bfloat162float(h1)); \
            __nv_bfloat16 l2 = __float2bfloat16(v[i].z - __bfloat162float(h2)); \
            __nv_bfloat16 l3 = __float2bfloat16(v[i].w - __bfloat162float(h3)); \
            uint32_t hA = (uint32_t)__bfloat16_as_ushort(h0) | ((uint32_t)__bfloat16_as_ushort(h1) << 16); \
            uint32_t hB = (uint32_t)__bfloat16_as_ushort(h2) | ((uint32_t)__bfloat16_as_ushort(h3) << 16); \
            uint32_t lA = (uint32_t)__bfloat16_as_ushort(l0) | ((uint32_t)__bfloat16_as_ushort(l1) << 16); \
            uint32_t lB = (uint32_t)__bfloat16_as_ushort(l2) | ((uint32_t)__bfloat16_as_ushort(l3) << 16); \
            asm volatile("st.shared.v2.b32 [%0], {%1,%2};" :: "r"(dh + i * 8), "r"(hA), "r"(hB));          \
            asm volatile("st.shared.v2.b32 [%0], {%1,%2};" :: "r"(dh + 10240 + i * 8), "r"(lA), "r"(lB));  \
        }                                                                       \
    } while (0)

    // prologue: fill stage 0
    LDG_A(0);
    CPA_B(0, 0);
    STS_A(0);
    CP_WAIT0();
    __syncthreads();

    for (int c = 0; c < CH1; ++c) {
        const int st  = c & 1;
        const int nst = st ^ 1;
        const bool pre = (c + 1 < CH1);
        if (pre) { LDG_A(c + 1); CPA_B(c + 1, nst); }

        // ---- compute on stage st ----
        const uint32_t abase = sb + st * G1_STG;
        const uint32_t bbase = abase + 20480;
#pragma unroll
        for (int ks = 0; ks < 2; ++ks) {
            const int kb = ks * 16;
            uint32_t ah[2][4], al[2][4], bh[4][4], bl[4][4];
#pragma unroll
            for (int mt = 0; mt < 2; ++mt) {
                uint32_t ra = abase + (uint32_t)((warp_m + mt * 16 + a_moff) * PITCH + (kb + a_koff) * 2);
                ldm_x4(ah[mt][0], ah[mt][1], ah[mt][2], ah[mt][3], ra);
                ldm_x4(al[mt][0], al[mt][1], al[mt][2], al[mt][3], ra + 10240);
            }
#pragma unroll
            for (int bb = 0; bb < 4; ++bb) {
                uint32_t rb = bbase + (uint32_t)((warp_n + bb * 16 + b_noff) * PITCH + (kb + b_koff) * 2);
                ldm_x4(bh[bb][0], bh[bb][1], bh[bb][2], bh[bb][3], rb);
                ldm_x4(bl[bb][0], bl[bb][1], bl[bb][2], bl[bb][3], rb + 10240);
            }
#pragma unroll
            for (int mt = 0; mt < 2; ++mt)
#pragma unroll
                for (int nt = 0; nt < 8; ++nt) {
                    const uint32_t* Bh = &bh[nt >> 1][(nt & 1) * 2];
                    const uint32_t* Bl = &bl[nt >> 1][(nt & 1) * 2];
                    mma16816(acc[mt][nt], ah[mt], Bh);
                    mma16816(acc[mt][nt], ah[mt], Bl);
                    mma16816(acc[mt][nt], al[mt], Bh);
                }
        }

        if (pre) { STS_A(nst); CP_WAIT0(); }
        __syncthreads();
    }

    // ---- epilogue: bias + relu, direct STG ----
    const int g  = lane >> 2;
    const int t2 = (lane & 3) * 2;
#pragma unroll
    for (int nt = 0; nt < 8; ++nt) {
        int n = n0g + warp_n + nt * 8 + t2;
        float b0 = bt[n], b1 = bt[n + 1];
#pragma unroll
        for (int mt = 0; mt < 2; ++mt) {
            int ma = m0 + warp_m + mt * 16 + g;
            if (ma < NN_NODES) {
                float2 o;
                o.x = fmaxf(acc[mt][nt][0] + b0, 0.f);
                o.y = fmaxf(acc[mt][nt][1] + b1, 0.f);
                *reinterpret_cast<float2*>(H + (size_t)ma * 256 + n) = o;
            }
            int mb = ma + 8;
            if (mb < NN_NODES) {
                float2 o;
                o.x = fmaxf(acc[mt][nt][2] + b0, 0.f);
                o.y = fmaxf(acc[mt][nt][3] + b1, 0.f);
                *reinterpret_cast<float2*>(H + (size_t)mb * 256 + n) = o;
            }
        }
    }
#undef LDG_A
#undef CPA_B
#undef STS_A
}

// ---------------- SpMM: one block per dst row, one thread per channel -------
template <int CH>
__global__ void __launch_bounds__(CH) k_spmm(const float* __restrict__ h,
                                             float* __restrict__ tx) {
    int d = blockIdx.x;
    int c = threadIdx.x;
    int beg = g_rowstart[d];
    int end = g_rowstart[d + 1];
    float acc = 0.0f;
    int j = beg;
    for (; j + 4 <= end; j += 4) {
        int   s0 = g_srcs[j],   s1 = g_srcs[j+1], s2 = g_srcs[j+2], s3 = g_srcs[j+3];
        float w0 = g_ws[j],     w1 = g_ws[j+1],   w2 = g_ws[j+2],   w3 = g_ws[j+3];
        float h0 = h[(size_t)s0 * CH + c];
        float h1 = h[(size_t)s1 * CH + c];
        float h2 = h[(size_t)s2 * CH + c];
        float h3 = h[(size_t)s3 * CH + c];
        acc += w0 * h0; acc += w1 * h1; acc += w2 * h2; acc += w3 * h3;
    }
    for (; j < end; ++j)
        acc += g_ws[j] * h[(size_t)g_srcs[j] * CH + c];
    tx[(size_t)d * CH + c] = acc;
}

// ---------------- SIMT SGEMM for the small GEMMs ----------------------------
template <int BM, int BN, int BK, int TM, int TN, bool RELU>
__global__ void __launch_bounds__((BM / TM) * (BN / TN))
k_gemm(const float* __restrict__ A1, const float* __restrict__ B1,
       const float* __restrict__ A2, const float* __restrict__ B2,
       const float* __restrict__ bias, float* __restrict__ C,
       int M, int N, int K) {
    constexpr int NT = (BM / TM) * (BN / TN);
    __shared__ float As[BK][BM];
    __shared__ float Bs[BK][BN];

    const int tid = threadIdx.x;
    const int m0 = blockIdx.y * BM;
    const int n0 = blockIdx.x * BN;
    const int tr = tid / (BN / TN);
    const int tc = tid % (BN / TN);
    const int rowBase = tr * TM;
    const int colBase = tc * TN;

    float acc[TM][TN];
#pragma unroll
    for (int i = 0; i < TM; i++)
#pragma unroll
        for (int j = 0; j < TN; j++) acc[i][j] = 0.0f;

    const int nphase = (A2 != nullptr) ? 2 : 1;
    for (int phase = 0; phase < nphase; ++phase) {
        const float* __restrict__ A = phase ? A2 : A1;
        const float* __restrict__ B = phase ? B2 : B1;
        for (int k0 = 0; k0 < K; k0 += BK) {
            constexpr int AIT = (BM * BK / 4) / NT;
#pragma unroll
            for (int it = 0; it < AIT; ++it) {
                int idx = tid + it * NT;
                int ar = idx / (BK / 4);
                int akg = idx % (BK / 4);
                int grow = m0 + ar;
                float4 f = make_float4(0.f, 0.f, 0.f, 0.f);
                if (grow < M)
                    f = *reinterpret_cast<const float4*>(A + (size_t)grow * K + k0 + akg * 4);
                As[akg * 4 + 0][ar] = f.x;
                As[akg * 4 + 1][ar] = f.y;
                As[akg * 4 + 2][ar] = f.z;
                As[akg * 4 + 3][ar] = f.w;
            }
            constexpr int BIT = (BK * BN) / NT;
#pragma unroll
            for (int it = 0; it < BIT; ++it) {
                int idx = tid + it * NT;
                int br = idx / BN;
                int bc = idx % BN;
                Bs[br][bc] = B[(size_t)(k0 + br) * N + n0 + bc];
            }
            __syncthreads();
#pragma unroll
            for (int k = 0; k < BK; k++) {
                float ra[TM], rb[TN];
#pragma unroll
                for (int i = 0; i < TM; i++) ra[i] = As[k][rowBase + i];
#pragma unroll
                for (int j = 0; j < TN; j++) rb[j] = Bs[k][colBase + j];
#pragma unroll
                for (int i = 0; i < TM; i++)
#pragma unroll
                    for (int j = 0; j < TN; j++)
                        acc[i][j] += ra[i] * rb[j];
            }
            __syncthreads();
        }
    }

    float bv[TN];
#pragma unroll
    for (int j = 0; j < TN; j++) bv[j] = bias[n0 + colBase + j];

#pragma unroll
    for (int i = 0; i < TM; i++) {
        int grow = m0 + rowBase + i;
        if (grow < M) {
            float4 o;
            float v0 = acc[i][0] + bv[0];
            float v1 = acc[i][1] + bv[1];
            float v2 = acc[i][2] + bv[2];
            float v3 = acc[i][3] + bv[3];
            if (RELU) {
                v0 = fmaxf(v0, 0.f); v1 = fmaxf(v1, 0.f);
                v2 = fmaxf(v2, 0.f); v3 = fmaxf(v3, 0.f);
            }
            o.x = v0; o.y = v1; o.z = v2; o.w = v3;
            *reinterpret_cast<float4*>(C + (size_t)grow * N + n0 + colBase) = o;
        }
    }
}

// ---------------- launcher --------------------------------------------------
extern "C" void kernel_launch(void* const* d_in, const int* in_sizes, int n_in,
                              void* d_out, int out_size) {
    const float* x    = (const float*)d_in[0];
    const int*   ei   = (const int*)d_in[1];
    const float* Wt   = (const float*)d_in[2];
    const float* bt   = (const float*)d_in[3];
    const float* W0_1 = (const float*)d_in[4];
    const float* W1_1 = (const float*)d_in[5];
    const float* b1   = (const float*)d_in[6];
    const float* W0mu = (const float*)d_in[7];
    const float* W1mu = (const float*)d_in[8];
    const float* bmu  = (const float*)d_in[9];
    const float* W0ls = (const float*)d_in[10];
    const float* W1ls = (const float*)d_in[11];
    const float* bls  = (const float*)d_in[12];
    float* out = (float*)d_out;

    float *h, *tx1, *h2, *tx2;
    cudaGetSymbolAddress((void**)&h,   g_h);
    cudaGetSymbolAddress((void**)&tx1, g_tx1);
    cudaGetSymbolAddress((void**)&h2,  g_h2);
    cudaGetSymbolAddress((void**)&tx2, g_tx2);

    cudaFuncSetAttribute(k_gemm1_mma, cudaFuncAttributeMaxDynamicSharedMemorySize, G1_SMEM);

    const int TPB = 256;

    // graph preprocessing
    k_zero_deg<<<(NN_NODES + TPB - 1) / TPB, TPB>>>(NN_NODES);
    k_count<<<(NE + TPB - 1) / TPB, TPB>>>(ei);
    k_dinv<<<(NN_NODES + TPB - 1) / TPB, TPB>>>(NN_NODES);
    k_scan<<<1, 1024>>>(NN_NODES);
    k_bucket<<<(NE + TPB - 1) / TPB, TPB>>>(ei);

    // Wt -> transposed bf16 hi/lo
    {
        dim3 grid(KPAD / 32, 256 / 32), blk(32, 32);
        k_convW<<<grid, blk>>>(Wt);
    }

    // h = relu(x @ Wt + bt) via mma.sync bf16 3-term split
    {
        dim3 grid(2, 79);
        k_gemm1_mma<<<grid, 256, G1_SMEM>>>(x, bt, h);
    }

    // tx1 = L_hat @ h
    k_spmm<IN_C><<<NN_NODES, IN_C>>>(h, tx1);

    // h2 = relu(h @ W0_1 + tx1 @ W1_1 + b1)
    {
        dim3 grid(C1 / 64, (NN_NODES + 127) / 128);
        k_gemm<128, 64, 8, 8, 4, true><<<grid, 256>>>(
            h, W0_1, tx1, W1_1, b1, h2, NN_NODES, C1, IN_C);
    }
    // tx2 = L_hat @ h2
    k_spmm<C1><<<NN_NODES, C1>>>(h2, tx2);

    // mu / logstd
    {
        dim3 grid(OUT_C / 64, (NN_NODES + 127) / 128);
        k_gemm<128, 64, 8, 8, 4, false><<<grid, 256>>>(
            h2, W0mu, tx2, W1mu, bmu, out, NN_NODES, OUT_C, C1);
        k_gemm<128, 64, 8, 8, 4, false><<<grid, 256>>>(
            h2, W0ls, tx2, W1ls, bls, out + NN_NODES * OUT_C, NN_NODES, OUT_C, C1);
    }
}

// round 5
// speedup vs baseline: 2.0165x; 1.8633x over previous
#include <cuda_runtime.h>
#include <cuda_bf16.h>
#include <cstdint>
#include <cstddef>

// ---------------- problem constants ----------------
#define NN_NODES 10000
#define IN_C     256
#define C1       128
#define OUT_C    64
#define NE       640000
#define KPAD     10048          // padded K for B (zero-filled)
#define BKC      32             // K per mainloop chunk
#define CH1      313            // ceil(10000/32)

// ---------------- PTX helpers ----------------
__device__ __forceinline__ uint32_t smem_u32(const void* p) {
    uint32_t a;
    asm("{ .reg .u64 t; cvta.to.shared.u64 t, %1; cvt.u32.u64 %0, t; }" : "=r"(a) : "l"(p));
    return a;
}
__device__ __forceinline__ void ldm_x4(uint32_t& r0, uint32_t& r1, uint32_t& r2, uint32_t& r3,
                                       uint32_t addr) {
    asm volatile("ldmatrix.sync.aligned.m8n8.x4.shared.b16 {%0,%1,%2,%3}, [%4];"
                 : "=r"(r0), "=r"(r1), "=r"(r2), "=r"(r3) : "r"(addr));
}
__device__ __forceinline__ void mma16816(float* d, const uint32_t* a, const uint32_t* b) {
    asm volatile("mma.sync.aligned.m16n8k16.row.col.f32.bf16.bf16.f32 "
                 "{%0,%1,%2,%3}, {%4,%5,%6,%7}, {%8,%9}, {%0,%1,%2,%3};"
                 : "+f"(d[0]), "+f"(d[1]), "+f"(d[2]), "+f"(d[3])
                 : "r"(a[0]), "r"(a[1]), "r"(a[2]), "r"(a[3]), "r"(b[0]), "r"(b[1]));
}
#define CP16(dst, src) \
    asm volatile("cp.async.cg.shared.global [%0], [%1], 16;" :: "r"(dst), "l"(src))
#define CP_COMMIT() asm volatile("cp.async.commit_group;")
#define CP_WAIT0()  asm volatile("cp.async.wait_group 0;")

// ---------------- scratch globals ----------------
__device__ float g_h   [NN_NODES * IN_C];
__device__ float g_tx1 [NN_NODES * IN_C];
__device__ float g_h2  [NN_NODES * C1];
__device__ float g_tx2 [NN_NODES * C1];
__device__ int   g_outdeg[NN_NODES];
__device__ int   g_indeg [NN_NODES];
__device__ float g_dinv  [NN_NODES];
__device__ int   g_rowstart[NN_NODES + 1];
__device__ int   g_cursor  [NN_NODES];
__device__ int   g_srcs [NE];
__device__ float g_ws   [NE];
__device__ __nv_bfloat16 g_BT_hi[256 * KPAD];   // Wt^T split-hi, [n][k]
__device__ __nv_bfloat16 g_BT_lo[256 * KPAD];   // Wt^T split-lo

// ---------------- preprocessing kernels ----------------
__global__ void k_zero_deg(int n) {
    int i = blockIdx.x * blockDim.x + threadIdx.x;
    if (i < n) { g_outdeg[i] = 0; g_indeg[i] = 0; }
}
__global__ void k_count(const int* __restrict__ ei) {
    int e = blockIdx.x * blockDim.x + threadIdx.x;
    if (e < NE) {
        atomicAdd(&g_outdeg[ei[e]], 1);
        atomicAdd(&g_indeg[ei[NE + e]], 1);
    }
}
__global__ void k_dinv(int n) {
    int i = blockIdx.x * blockDim.x + threadIdx.x;
    if (i < n) {
        int d = g_outdeg[i];
        g_dinv[i] = (d > 0) ? rsqrtf((float)d) : 0.0f;
    }
}
// one-pass scan: each thread owns 10 rows
__global__ void k_scan(int n) {
    __shared__ int sh[1024];
    int t = threadIdx.x;
    const int per = 10;
    int base = t * per;
    int loc[10];
    int s = 0;
#pragma unroll
    for (int i = 0; i < per; i++) {
        int idx = base + i;
        int v = (idx < n) ? g_indeg[idx] : 0;
        loc[i] = s; s += v;
    }
    sh[t] = s;
    __syncthreads();
    for (int off = 1; off < 1024; off <<= 1) {
        int v = (t >= off) ? sh[t - off] : 0;
        __syncthreads();
        sh[t] += v;
        __syncthreads();
    }
    int bb = (t > 0) ? sh[t - 1] : 0;
#pragma unroll
    for (int i = 0; i < per; i++) {
        int idx = base + i;
        if (idx < n) { int v = bb + loc[i]; g_rowstart[idx] = v; g_cursor[idx] = v; }
    }
    if (t == 1023) g_rowstart[n] = sh[1023];
}
__global__ void k_bucket(const int* __restrict__ ei) {
    int e = blockIdx.x * blockDim.x + threadIdx.x;
    if (e < NE) {
        int s = ei[e];
        int d = ei[NE + e];
        int pos = atomicAdd(&g_cursor[d], 1);
        g_srcs[pos] = s;
        g_ws[pos]   = -g_dinv[s] * g_dinv[d];
    }
}

// Wt [10000,256] fp32 -> transposed bf16 hi/lo [256][KPAD]
__global__ void k_convW(const float* __restrict__ Wt) {
    __shared__ float tile[32][33];
    int bx = blockIdx.x, by = blockIdx.y;
    int tx = threadIdx.x, ty = threadIdx.y;
    int gk = bx * 32 + ty;
    int gn = by * 32 + tx;
    tile[ty][tx] = (gk < NN_NODES) ? Wt[(size_t)gk * 256 + gn] : 0.0f;
    __syncthreads();
    int n = by * 32 + ty;
    int k = bx * 32 + tx;
    float v = tile[tx][ty];
    __nv_bfloat16 hi = __float2bfloat16(v);
    __nv_bfloat16 lo = __float2bfloat16(v - __bfloat162float(hi));
    g_BT_hi[(size_t)n * KPAD + k] = hi;
    g_BT_lo[(size_t)n * KPAD + k] = lo;
}

// ---------------- GEMM1 via mma.sync bf16 (3-term split) --------------------
// H = relu(X @ Wt + bt). CTA tile 64x128, BK=32, 2-stage smem, 2 CTAs/SM.
// smem per stage (pitch 80B/row): Ahi@0(5120), Alo@5120, Bhi@10240(10240), Blo@20480.
#define G1_STG   30720
#define G1_SMEM  (2 * G1_STG)
#define PITCH    80

__global__ void __launch_bounds__(256, 2)
k_gemm1_mma(const float* __restrict__ X, const float* __restrict__ bt,
            float* __restrict__ H) {
    extern __shared__ char smem[];
    const uint32_t sb = smem_u32(smem);
    const int tid  = threadIdx.x;
    const int wid  = tid >> 5, lane = tid & 31;
    const int m0   = blockIdx.y * 64;
    const int n0g  = blockIdx.x * 128;
    const int warp_m = (wid >> 2) * 32;     // 2 m-warps
    const int warp_n = (wid & 3) * 32;      // 4 n-warps

    // A loader coords: 64 rows x 4 threads/row, 8 floats each
    const int alr = tid >> 2;
    const int alq = tid & 3;
    // B loader coords: 128 rows x 2 threads/row
    const int blr = tid >> 1;
    const int blh = tid & 1;

    // ldmatrix lane offsets
    const int La     = lane & 7;
    const int a_moff = ((lane >> 3) & 1) * 8 + La;
    const int a_koff = (lane >> 4) * 8;
    const int b_noff = (lane >> 4) * 8 + La;
    const int b_koff = ((lane >> 3) & 1) * 8;

    float acc[2][4][4];
#pragma unroll
    for (int i = 0; i < 2; i++)
#pragma unroll
        for (int j = 0; j < 4; j++)
#pragma unroll
            for (int q = 0; q < 4; q++) acc[i][j][q] = 0.0f;

    const char* bhsrc = (const char*)g_BT_hi;
    const char* blsrc = (const char*)g_BT_lo;
    const size_t brow = (size_t)KPAD * 2;

    float4 v[2];

#define LDG_A(c) do {                                                           \
        int k0 = (c) * BKC;                                                     \
        int grow = m0 + alr;                                                    \
        _Pragma("unroll")                                                       \
        for (int i = 0; i < 2; i++) {                                           \
            int gk = k0 + alq * 8 + i * 4;                                      \
            v[i] = (grow < NN_NODES && gk < NN_NODES)                           \
                 ? *reinterpret_cast<const float4*>(X + (size_t)grow * NN_NODES + gk) \
                 : make_float4(0.f, 0.f, 0.f, 0.f);                             \
        }                                                                       \
    } while (0)

#define CPA_B(c, st) do {                                                       \
        int k0 = (c) * BKC;                                                     \
        uint32_t dsth = sb + (st) * G1_STG + 10240 + blr * PITCH + blh * 32;    \
        const char* sh_ = bhsrc + (size_t)(n0g + blr) * brow + k0 * 2 + blh * 32; \
        const char* sl_ = blsrc + (size_t)(n0g + blr) * brow + k0 * 2 + blh * 32; \
        CP16(dsth,       sh_);      CP16(dsth + 16,         sh_ + 16);          \
        CP16(dsth+10240, sl_);      CP16(dsth + 10240 + 16, sl_ + 16);          \
        CP_COMMIT();                                                            \
    } while (0)

#define STS_A(st) do {                                                          \
        uint32_t dh = sb + (st) * G1_STG + alr * PITCH + alq * 16;              \
        uint32_t hA[4], lA[4];                                                  \
        _Pragma("unroll")                                                       \
        for (int i = 0; i < 2; i++) {                                           \
            __nv_bfloat16 h0 = __float2bfloat16(v[i].x);                        \
            __nv_bfloat16 h1 = __float2bfloat16(v[i].y);                        \
            __nv_bfloat16 h2 = __float2bfloat16(v[i].z);                        \
            __nv_bfloat16 h3 = __float2bfloat16(v[i].w);                        \
            __nv_bfloat16 l0 = __float2bfloat16(v[i].x - __bfloat162float(h0)); \
            __nv_bfloat16 l1 = __float2bfloat16(v[i].y - __bfloat162float(h1)); \
            __nv_bfloat16 l2 = __float2bfloat16(v[i].z - __bfloat162float(h2)); \
            __nv_bfloat16 l3 = __float2bfloat16(v[i].w - __bfloat162float(h3)); \
            hA[i*2+0] = (uint32_t)__bfloat16_as_ushort(h0) | ((uint32_t)__bfloat16_as_ushort(h1) << 16); \
            hA[i*2+1] = (uint32_t)__bfloat16_as_ushort(h2) | ((uint32_t)__bfloat16_as_ushort(h3) << 16); \
            lA[i*2+0] = (uint32_t)__bfloat16_as_ushort(l0) | ((uint32_t)__bfloat16_as_ushort(l1) << 16); \
            lA[i*2+1] = (uint32_t)__bfloat16_as_ushort(l2) | ((uint32_t)__bfloat16_as_ushort(l3) << 16); \
        }                                                                       \
        asm volatile("st.shared.v4.b32 [%0], {%1,%2,%3,%4};"                    \
            :: "r"(dh), "r"(hA[0]), "r"(hA[1]), "r"(hA[2]), "r"(hA[3]));        \
        asm volatile("st.shared.v4.b32 [%0], {%1,%2,%3,%4};"                    \
            :: "r"(dh + 5120), "r"(lA[0]), "r"(lA[1]), "r"(lA[2]), "r"(lA[3])); \
    } while (0)

    // prologue: fill stage 0
    LDG_A(0);
    CPA_B(0, 0);
    STS_A(0);
    CP_WAIT0();
    __syncthreads();

    for (int c = 0; c < CH1; ++c) {
        const int st  = c & 1;
        const int nst = st ^ 1;
        const bool pre = (c + 1 < CH1);
        if (pre) { LDG_A(c + 1); CPA_B(c + 1, nst); }

        const uint32_t abase = sb + st * G1_STG;
        const uint32_t bbase = abase + 10240;
#pragma unroll
        for (int ks = 0; ks < 2; ++ks) {
            const int kb = ks * 16;
            uint32_t ah[2][4], al[2][4], bh[2][4], bl[2][4];
#pragma unroll
            for (int mt = 0; mt < 2; ++mt) {
                uint32_t ra = abase + (uint32_t)((warp_m + mt * 16 + a_moff) * PITCH + (kb + a_koff) * 2);
                ldm_x4(ah[mt][0], ah[mt][1], ah[mt][2], ah[mt][3], ra);
                ldm_x4(al[mt][0], al[mt][1], al[mt][2], al[mt][3], ra + 5120);
            }
#pragma unroll
            for (int bb = 0; bb < 2; ++bb) {
                uint32_t rb = bbase + (uint32_t)((warp_n + bb * 16 + b_noff) * PITCH + (kb + b_koff) * 2);
                ldm_x4(bh[bb][0], bh[bb][1], bh[bb][2], bh[bb][3], rb);
                ldm_x4(bl[bb][0], bl[bb][1], bl[bb][2], bl[bb][3], rb + 10240);
            }
#pragma unroll
            for (int mt = 0; mt < 2; ++mt)
#pragma unroll
                for (int nt = 0; nt < 4; ++nt) {
                    const uint32_t* Bh = &bh[nt >> 1][(nt & 1) * 2];
                    const uint32_t* Bl = &bl[nt >> 1][(nt & 1) * 2];
                    mma16816(acc[mt][nt], ah[mt], Bh);
                    mma16816(acc[mt][nt], ah[mt], Bl);
                    mma16816(acc[mt][nt], al[mt], Bh);
                }
        }

        if (pre) { STS_A(nst); CP_WAIT0(); }
        __syncthreads();
    }

    // ---- epilogue: bias + relu, direct STG ----
    const int g  = lane >> 2;
    const int t2 = (lane & 3) * 2;
#pragma unroll
    for (int nt = 0; nt < 4; ++nt) {
        int n = n0g + warp_n + nt * 8 + t2;
        float b0 = bt[n], b1 = bt[n + 1];
#pragma unroll
        for (int mt = 0; mt < 2; ++mt) {
            int ma = m0 + warp_m + mt * 16 + g;
            if (ma < NN_NODES) {
                float2 o;
                o.x = fmaxf(acc[mt][nt][0] + b0, 0.f);
                o.y = fmaxf(acc[mt][nt][1] + b1, 0.f);
                *reinterpret_cast<float2*>(H + (size_t)ma * 256 + n) = o;
            }
            int mb = ma + 8;
            if (mb < NN_NODES) {
                float2 o;
                o.x = fmaxf(acc[mt][nt][2] + b0, 0.f);
                o.y = fmaxf(acc[mt][nt][3] + b1, 0.f);
                *reinterpret_cast<float2*>(H + (size_t)mb * 256 + n) = o;
            }
        }
    }
#undef LDG_A
#undef CPA_B
#undef STS_A
}

// ---------------- SpMM: one block per dst row, one thread per channel -------
template <int CH>
__global__ void __launch_bounds__(CH) k_spmm(const float* __restrict__ h,
                                             float* __restrict__ tx) {
    int d = blockIdx.x;
    int c = threadIdx.x;
    int beg = g_rowstart[d];
    int end = g_rowstart[d + 1];
    float acc = 0.0f;
    int j = beg;
    for (; j + 4 <= end; j += 4) {
        int   s0 = g_srcs[j],   s1 = g_srcs[j+1], s2 = g_srcs[j+2], s3 = g_srcs[j+3];
        float w0 = g_ws[j],     w1 = g_ws[j+1],   w2 = g_ws[j+2],   w3 = g_ws[j+3];
        float h0 = h[(size_t)s0 * CH + c];
        float h1 = h[(size_t)s1 * CH + c];
        float h2 = h[(size_t)s2 * CH + c];
        float h3 = h[(size_t)s3 * CH + c];
        acc += w0 * h0; acc += w1 * h1; acc += w2 * h2; acc += w3 * h3;
    }
    for (; j < end; ++j)
        acc += g_ws[j] * h[(size_t)g_srcs[j] * CH + c];
    tx[(size_t)d * CH + c] = acc;
}

// ---------------- SIMT SGEMM for the small GEMMs ----------------------------
template <int BM, int BN, int BK, int TM, int TN, bool RELU>
__global__ void __launch_bounds__((BM / TM) * (BN / TN))
k_gemm(const float* __restrict__ A1, const float* __restrict__ B1,
       const float* __restrict__ A2, const float* __restrict__ B2,
       const float* __restrict__ bias, float* __restrict__ C,
       int M, int N, int K) {
    constexpr int NT = (BM / TM) * (BN / TN);
    __shared__ float As[BK][BM];
    __shared__ float Bs[BK][BN];

    const int tid = threadIdx.x;
    const int m0 = blockIdx.y * BM;
    const int n0 = blockIdx.x * BN;
    const int tr = tid / (BN / TN);
    const int tc = tid % (BN / TN);
    const int rowBase = tr * TM;
    const int colBase = tc * TN;

    float acc[TM][TN];
#pragma unroll
    for (int i = 0; i < TM; i++)
#pragma unroll
        for (int j = 0; j < TN; j++) acc[i][j] = 0.0f;

    const int nphase = (A2 != nullptr) ? 2 : 1;
    for (int phase = 0; phase < nphase; ++phase) {
        const float* __restrict__ A = phase ? A2 : A1;
        const float* __restrict__ B = phase ? B2 : B1;
        for (int k0 = 0; k0 < K; k0 += BK) {
            constexpr int AIT = (BM * BK / 4) / NT;
#pragma unroll
            for (int it = 0; it < AIT; ++it) {
                int idx = tid + it * NT;
                int ar = idx / (BK / 4);
                int akg = idx % (BK / 4);
                int grow = m0 + ar;
                float4 f = make_float4(0.f, 0.f, 0.f, 0.f);
                if (grow < M)
                    f = *reinterpret_cast<const float4*>(A + (size_t)grow * K + k0 + akg * 4);
                As[akg * 4 + 0][ar] = f.x;
                As[akg * 4 + 1][ar] = f.y;
                As[akg * 4 + 2][ar] = f.z;
                As[akg * 4 + 3][ar] = f.w;
            }
            constexpr int BIT = (BK * BN) / NT;
#pragma unroll
            for (int it = 0; it < BIT; ++it) {
                int idx = tid + it * NT;
                int br = idx / BN;
                int bc = idx % BN;
                Bs[br][bc] = B[(size_t)(k0 + br) * N + n0 + bc];
            }
            __syncthreads();
#pragma unroll
            for (int k = 0; k < BK; k++) {
                float ra[TM], rb[TN];
#pragma unroll
                for (int i = 0; i < TM; i++) ra[i] = As[k][rowBase + i];
#pragma unroll
                for (int j = 0; j < TN; j++) rb[j] = Bs[k][colBase + j];
#pragma unroll
                for (int i = 0; i < TM; i++)
#pragma unroll
                    for (int j = 0; j < TN; j++)
                        acc[i][j] += ra[i] * rb[j];
            }
            __syncthreads();
        }
    }

    float bv[TN];
#pragma unroll
    for (int j = 0; j < TN; j++) bv[j] = bias[n0 + colBase + j];

#pragma unroll
    for (int i = 0; i < TM; i++) {
        int grow = m0 + rowBase + i;
        if (grow < M) {
            float4 o;
            float v0 = acc[i][0] + bv[0];
            float v1 = acc[i][1] + bv[1];
            float v2 = acc[i][2] + bv[2];
            float v3 = acc[i][3] + bv[3];
            if (RELU) {
                v0 = fmaxf(v0, 0.f); v1 = fmaxf(v1, 0.f);
                v2 = fmaxf(v2, 0.f); v3 = fmaxf(v3, 0.f);
            }
            o.x = v0; o.y = v1; o.z = v2; o.w = v3;
            *reinterpret_cast<float4*>(C + (size_t)grow * N + n0 + colBase) = o;
        }
    }
}

// ---------------- launcher --------------------------------------------------
extern "C" void kernel_launch(void* const* d_in, const int* in_sizes, int n_in,
                              void* d_out, int out_size) {
    const float* x    = (const float*)d_in[0];
    const int*   ei   = (const int*)d_in[1];
    const float* Wt   = (const float*)d_in[2];
    const float* bt   = (const float*)d_in[3];
    const float* W0_1 = (const float*)d_in[4];
    const float* W1_1 = (const float*)d_in[5];
    const float* b1   = (const float*)d_in[6];
    const float* W0mu = (const float*)d_in[7];
    const float* W1mu = (const float*)d_in[8];
    const float* bmu  = (const float*)d_in[9];
    const float* W0ls = (const float*)d_in[10];
    const float* W1ls = (const float*)d_in[11];
    const float* bls  = (const float*)d_in[12];
    float* out = (float*)d_out;

    float *h, *tx1, *h2, *tx2;
    cudaGetSymbolAddress((void**)&h,   g_h);
    cudaGetSymbolAddress((void**)&tx1, g_tx1);
    cudaGetSymbolAddress((void**)&h2,  g_h2);
    cudaGetSymbolAddress((void**)&tx2, g_tx2);

    cudaFuncSetAttribute(k_gemm1_mma, cudaFuncAttributeMaxDynamicSharedMemorySize, G1_SMEM);

    const int TPB = 256;

    // GEMM1 dependencies first, so k_gemm1_mma lands at launch index 3 (where
    // ncu has been sampling) — graph preprocessing is independent and follows.
    {
        dim3 grid(KPAD / 32, 256 / 32), blk(32, 32);
        k_convW<<<grid, blk>>>(Wt);                              // 0
    }
    k_zero_deg<<<(NN_NODES + TPB - 1) / TPB, TPB>>>(NN_NODES);   // 1
    k_count<<<(NE + TPB - 1) / TPB, TPB>>>(ei);                  // 2
    {
        dim3 grid(2, 157);
        k_gemm1_mma<<<grid, 256, G1_SMEM>>>(x, bt, h);           // 3
    }
    k_dinv<<<(NN_NODES + TPB - 1) / TPB, TPB>>>(NN_NODES);       // 4
    k_scan<<<1, 1024>>>(NN_NODES);                               // 5
    k_bucket<<<(NE + TPB - 1) / TPB, TPB>>>(ei);                 // 6

    // tx1 = L_hat @ h
    k_spmm<IN_C><<<NN_NODES, IN_C>>>(h, tx1);

    // h2 = relu(h @ W0_1 + tx1 @ W1_1 + b1)
    {
        dim3 grid(C1 / 64, (NN_NODES + 127) / 128);
        k_gemm<128, 64, 8, 8, 4, true><<<grid, 256>>>(
            h, W0_1, tx1, W1_1, b1, h2, NN_NODES, C1, IN_C);
    }
    // tx2 = L_hat @ h2
    k_spmm<C1><<<NN_NODES, C1>>>(h2, tx2);

    // mu / logstd
    {
        dim3 grid(OUT_C / 64, (NN_NODES + 127) / 128);
        k_gemm<128, 64, 8, 8, 4, false><<<grid, 256>>>(
            h2, W0mu, tx2, W1mu, bmu, out, NN_NODES, OUT_C, C1);
        k_gemm<128, 64, 8, 8, 4, false><<<grid, 256>>>(
            h2, W0ls, tx2, W1ls, bls, out + NN_NODES * OUT_C, NN_NODES, OUT_C, C1);
    }
}